// round 13
// baseline (speedup 1.0000x reference)
#include <cuda_runtime.h>
#include <cstdint>

// Problem constants
#define BB 32
#define II 2048
#define OO 32
#define CC 16
#define UU 32
#define KTOT (II*CC)        // 32768

// D[1024(m=o*32+u), 32(n=b)] = W^T * X^T
#define MT  8               // m-tiles of 128 rows (4 o x 32 u)
#define KS  64              // k-splits
#define KC  32              // k per chunk (2 i's)
#define NCH (KTOT/(KS*KC))  // 16 chunks per block

#define ISTRIDE (OO*CC*UU)  // floats between consecutive i in w

// Scratch: partials [mt][ks][m_local(128)][b(32)] = 8MB
__device__ float g_spart[(size_t)MT * KS * 128 * BB];

// ---------------------------------------------------------------------------
__device__ __forceinline__ uint32_t smem_u32(const void* p) {
    uint32_t a;
    asm("{ .reg .u64 t; cvta.to.shared.u64 t, %1; cvt.u32.u64 %0, t; }"
        : "=r"(a) : "l"(p));
    return a;
}
// pack two f32 -> bf16x2, first arg in bits[15:0]
__device__ __forceinline__ uint32_t pack_bf16(float lo, float hi) {
    uint32_t r;
    asm("cvt.rn.bf16x2.f32 %0, %1, %2;" : "=r"(r) : "f"(hi), "f"(lo));
    return r;
}
__device__ __forceinline__ void mma_bf16(float* d, const uint32_t* a,
                                         uint32_t b0, uint32_t b1) {
    asm volatile(
        "mma.sync.aligned.m16n8k16.row.col.f32.bf16.bf16.f32 "
        "{%0,%1,%2,%3}, {%4,%5,%6,%7}, {%8,%9}, {%0,%1,%2,%3};"
        : "+f"(d[0]), "+f"(d[1]), "+f"(d[2]), "+f"(d[3])
        : "r"(a[0]), "r"(a[1]), "r"(a[2]), "r"(a[3]), "r"(b0), "r"(b1));
}
__device__ __forceinline__ void cp_async16(uint32_t saddr, const void* gaddr) {
    asm volatile("cp.async.cg.shared.global [%0], [%1], 16;"
                 :: "r"(saddr), "l"(gaddr));
}
__device__ __forceinline__ void cp_commit() {
    asm volatile("cp.async.commit_group;");
}
template <int N>
__device__ __forceinline__ void cp_wait() {
    asm volatile("cp.async.wait_group %0;" :: "n"(N));
}

// A fp32 smem [k(32)][m(128)]: element (k,m) at
//   k*128 + (((m>>2) ^ (k&7)) << 2) + (m&3)        (floats)
__device__ __forceinline__ int aidx(int k, int m) {
    return k * 128 + ((((m >> 2) ^ (k & 7)) << 2) | (m & 3));
}
// B fp32 smem [b(32)][k(32)]: element (b,k) at
//   b*32 + (((k>>2) ^ (b&7)) << 2) + (k&3)
__device__ __forceinline__ int bidx(int b, int k) {
    return b * 32 + ((((k >> 2) ^ (b & 7)) << 2) | (k & 3));
}

// ---------------------------------------------------------------------------
// GEMM: grid (MT, KS), 128 threads, 5 CTAs/SM.
// cp.async stages fp32 chunks (A [k][m], B [b][k], swizzled, double-buffered).
// Fragments gathered by plain LDS (round-10 fragment map), converted to
// bf16 hi/lo in registers, 48 HMMA per warp per chunk. No ldmatrix.
// ---------------------------------------------------------------------------
__global__ void __launch_bounds__(128, 5) gemm_tc(const float* __restrict__ w,
                                                  const float* __restrict__ x) {
    __shared__ __align__(16) float Afp[2][32 * 128];   // 2 x 16KB
    __shared__ __align__(16) float Bfp[2][32 * 32];    // 2 x 4KB

    const int mt   = blockIdx.x;
    const int ks   = blockIdx.y;
    const int tid  = threadIdx.x;
    const int wid  = tid >> 5;
    const int lane = tid & 31;
    const int g    = lane >> 2;
    const int t2   = (lane & 3) * 2;

    const int o0 = mt * 4;
    const int i_base = ks * (NCH * 2);        // first i of this block
    const int k0 = ks * (NCH * KC);           // first k in x

    const uint32_t sA0 = smem_u32(Afp[0]), sA1 = smem_u32(Afp[1]);
    const uint32_t sB0 = smem_u32(Bfp[0]), sB1 = smem_u32(Bfp[1]);

    // ---- chunk loader: A = 16KB (2 i x 4 o x 16 c x 32 u), B = 4KB
    auto issue = [&](int t, int p) {
        const uint32_t sA = p ? sA1 : sA0;
        const uint32_t sB = p ? sB1 : sB0;
        const float* wsrc =
            w + ((size_t)(i_base + 2 * t) * OO + o0) * (CC * UU);
#pragma unroll
        for (int r = 0; r < 8; r++) {
            const int e    = r * 128 + tid;           // 0..1023 16B pieces
            const int iloc = e >> 9;
            const int oloc = (e >> 7) & 3;
            const int c    = (e >> 3) & 15;
            const int u4   = e & 7;
            const float* gp = wsrc + ((size_t)(iloc * OO + oloc) * CC + c) * UU
                              + u4 * 4;
            const int k  = iloc * 16 + c;
            const int m4 = oloc * 8 + u4;             // m-group-of-4
            const int si = k * 128 + ((m4 ^ (k & 7)) << 2);
            cp_async16(sA + si * 4, gp);
        }
#pragma unroll
        for (int r = 0; r < 2; r++) {
            const int e = r * 128 + tid;              // 0..255 16B pieces
            const int b = e >> 3;
            const int j = e & 7;
            const float* gp = x + (size_t)b * KTOT + k0 + t * KC + j * 4;
            const int si = b * 32 + ((j ^ (b & 7)) << 2);
            cp_async16(sB + si * 4, gp);
        }
        cp_commit();
    };

    float acc[2][4][4];
#pragma unroll
    for (int a = 0; a < 2; a++)
#pragma unroll
        for (int b = 0; b < 4; b++)
#pragma unroll
            for (int c = 0; c < 4; c++) acc[a][b][c] = 0.f;

    issue(0, 0);

    for (int t = 0; t < NCH; t++) {
        const int p = t & 1;
        if (t + 1 < NCH) {
            issue(t + 1, p ^ 1);
            cp_wait<1>();
        } else {
            cp_wait<0>();
        }
        __syncthreads();   // chunk t fully in smem for all warps

        const float* A = Afp[p];
        const float* B = Bfp[p];

#pragma unroll
        for (int kt = 0; kt < 2; kt++) {
            const int tk = kt * 16 + t2;

            // ---- B fragments: (n = nt*8+g, k-pair at tk / tk+8)
            float2 bf[4][2];
#pragma unroll
            for (int nt = 0; nt < 4; nt++)
#pragma unroll
                for (int h = 0; h < 2; h++) {
                    const int koff = tk + h * 8;
                    bf[nt][h] = *(const float2*)&B[bidx(nt * 8 + g, koff)];
                }
            uint32_t bh[4][2], bl[4][2];
#pragma unroll
            for (int nt = 0; nt < 4; nt++)
#pragma unroll
                for (int h = 0; h < 2; h++) {
                    float2 v = bf[nt][h];
                    uint32_t hi = pack_bf16(v.x, v.y);
                    float r0 = v.x - __uint_as_float(hi << 16);
                    float r1 = v.y - __uint_as_float(hi & 0xffff0000u);
                    bh[nt][h] = hi;
                    bl[nt][h] = pack_bf16(r0, r1);
                }

            // ---- A fragments per m2, convert, MMA
#pragma unroll
            for (int m2 = 0; m2 < 2; m2++) {
                const int m0 = wid * 32 + m2 * 16 + g;
                float av[8];
                av[0] = A[aidx(tk,     m0)];
                av[1] = A[aidx(tk + 1, m0)];
                av[2] = A[aidx(tk,     m0 + 8)];
                av[3] = A[aidx(tk + 1, m0 + 8)];
                av[4] = A[aidx(tk + 8, m0)];
                av[5] = A[aidx(tk + 9, m0)];
                av[6] = A[aidx(tk + 8, m0 + 8)];
                av[7] = A[aidx(tk + 9, m0 + 8)];

                uint32_t ah[4], al[4];
#pragma unroll
                for (int q = 0; q < 4; q++) {
                    uint32_t hi = pack_bf16(av[2 * q], av[2 * q + 1]);
                    float r0 = av[2 * q]     - __uint_as_float(hi << 16);
                    float r1 = av[2 * q + 1] - __uint_as_float(hi & 0xffff0000u);
                    ah[q] = hi;
                    al[q] = pack_bf16(r0, r1);
                }
#pragma unroll
                for (int nt = 0; nt < 4; nt++) {
                    mma_bf16(acc[m2][nt], ah, bh[nt][0], bh[nt][1]);
                    mma_bf16(acc[m2][nt], al, bh[nt][0], bh[nt][1]);
                    mma_bf16(acc[m2][nt], ah, bl[nt][0], bl[nt][1]);
                }
            }
        }

        __syncthreads();   // all reads of buf p done before it is refilled
    }

    // ---- epilogue: D fragments -> g_spart[(mt*KS+ks)][m_local][b]
    float* outp = g_spart + ((size_t)(mt * KS + ks)) * (128 * BB);
#pragma unroll
    for (int m2 = 0; m2 < 2; m2++)
#pragma unroll
        for (int nt = 0; nt < 4; nt++) {
            const int r0 = wid * 32 + m2 * 16 + g;
            const int c  = nt * 8 + t2;
            *(float2*)(outp + (size_t)r0 * BB + c) =
                make_float2(acc[m2][nt][0], acc[m2][nt][1]);
            *(float2*)(outp + (size_t)(r0 + 8) * BB + c) =
                make_float2(acc[m2][nt][2], acc[m2][nt][3]);
        }
}

// ---------------------------------------------------------------------------
// Fused reduce + squash: grid (OO, 4), 1024 threads.
// ---------------------------------------------------------------------------
__global__ void __launch_bounds__(1024) reduce_squash(float* __restrict__ out) {
    const int o  = blockIdx.x;
    const int b0 = blockIdx.y * 8;
    const int t  = threadIdx.x;
    const int mt = o >> 2;

    __shared__ float4 smq[16][32][2];  // [kp][u][q]
    __shared__ float fin[32][9];       // [u][b-sub], pad 9
    __shared__ float scale_s[8];

    {   // phase 1
        const int q  = t & 1;
        const int uu = (t >> 1) & 31;
        const int kp = t >> 6;
        const int mrow = (o & 3) * 32 + uu;
        const float4* p = (const float4*)(g_spart +
            (((size_t)mt * KS + kp * 4) * 128 + mrow) * BB + b0) + q;
        float4 s = make_float4(0.f, 0.f, 0.f, 0.f);
#pragma unroll
        for (int j = 0; j < 4; j++) {
            float4 v = p[(size_t)j * (128 * BB / 4)];
            s.x += v.x; s.y += v.y; s.z += v.z; s.w += v.w;
        }
        smq[kp][uu][q] = s;
    }
    __syncthreads();

    if (t < 256) {   // phase 2: fold 16 kp slices
        const int u2 = t >> 3, bb = t & 7;
        float r = 0.f;
#pragma unroll
        for (int kp = 0; kp < 16; kp++) {
            float4 v = smq[kp][u2][bb >> 2];
            r += (&v.x)[bb & 3];
        }
        fin[u2][bb] = r;
    }
    __syncthreads();

    if (t < 8) {     // phase 3: per-b norm & scale
        float nsq = 0.f;
#pragma unroll
        for (int uv = 0; uv < UU; uv++) {
            float sv = fin[uv][t];
            nsq += sv * sv;
        }
        scale_s[t] = sqrtf(nsq) / (1.0f + nsq);
    }
    __syncthreads();

    if (t < 256) {   // phase 4: coalesced output
        const int u3 = t & 31, bb3 = t >> 5;
        out[(size_t)(b0 + bb3) * (OO * UU) + o * UU + u3] =
            fin[u3][bb3] * scale_s[bb3];
    }
}

// ---------------------------------------------------------------------------
extern "C" void kernel_launch(void* const* d_in, const int* in_sizes, int n_in,
                              void* d_out, int out_size) {
    const float* x = (const float*)d_in[0];
    const float* w = (const float*)d_in[1];
    if (n_in >= 2 && in_sizes[0] > in_sizes[1]) {   // guard input ordering
        x = (const float*)d_in[1];
        w = (const float*)d_in[0];
    }

    gemm_tc<<<dim3(MT, KS), 128>>>(w, x);
    reduce_squash<<<dim3(OO, 4), 1024>>>((float*)d_out);
}

// round 14
// speedup vs baseline: 1.1577x; 1.1577x over previous
#include <cuda_runtime.h>
#include <cstdint>

// Problem constants
#define BB 32
#define II 2048
#define OO 32
#define CC 16
#define UU 32
#define KTOT (II*CC)        // 32768

// D[1024(m=o*32+u), 32(n=b)] = W^T * X^T
#define MT  8               // m-tiles of 128 rows (4 o x 32 u)
#define KS  64              // k-splits
#define KC  32              // k per chunk (2 i's)
#define NCH (KTOT/(KS*KC))  // 16 chunks per block

#define ISTRIDE (OO*CC*UU)  // floats between consecutive i in w

// Accumulator [o][u][b] = 128KB. Zero at module load; reduce_squash restores
// zeros after reading, so every kernel_launch (and graph replay) sees zeros.
__device__ float g_acc[(size_t)OO * UU * BB];

// ---------------------------------------------------------------------------
__device__ __forceinline__ uint32_t smem_u32(const void* p) {
    uint32_t a;
    asm("{ .reg .u64 t; cvta.to.shared.u64 t, %1; cvt.u32.u64 %0, t; }"
        : "=r"(a) : "l"(p));
    return a;
}
// pack two f32 -> bf16x2, lo in bits[15:0]
__device__ __forceinline__ uint32_t pack_bf16(float lo, float hi) {
    uint32_t r;
    asm("cvt.rn.bf16x2.f32 %0, %1, %2;" : "=r"(r) : "f"(hi), "f"(lo));
    return r;
}
__device__ __forceinline__ void ldsm_x4(uint32_t* r, uint32_t addr) {
    asm volatile("ldmatrix.sync.aligned.m8n8.x4.shared.b16 {%0,%1,%2,%3}, [%4];"
                 : "=r"(r[0]), "=r"(r[1]), "=r"(r[2]), "=r"(r[3]) : "r"(addr));
}
__device__ __forceinline__ void mma_bf16(float* d, const uint32_t* a,
                                         uint32_t b0, uint32_t b1) {
    asm volatile(
        "mma.sync.aligned.m16n8k16.row.col.f32.bf16.bf16.f32 "
        "{%0,%1,%2,%3}, {%4,%5,%6,%7}, {%8,%9}, {%0,%1,%2,%3};"
        : "+f"(d[0]), "+f"(d[1]), "+f"(d[2]), "+f"(d[3])
        : "r"(a[0]), "r"(a[1]), "r"(a[2]), "r"(a[3]), "r"(b0), "r"(b1));
}

// 64B-row swizzle: 16B group j of row r lives at r*64 + ((j ^ ((r>>1)&3))<<4)
__device__ __forceinline__ uint32_t sw64(int row, int grp) {
    return (uint32_t)(row * 64 + ((grp ^ ((row >> 1) & 3)) << 4));
}

// ---------------------------------------------------------------------------
// GEMM (validated round-7/11 core, UNCHANGED except epilogue -> atomicAdd):
// grid (MT, KS), 128 threads, 4 CTAs/SM, prefetch above barrier.
// ---------------------------------------------------------------------------
__global__ void __launch_bounds__(128, 4) gemm_tc(const float* __restrict__ w,
                                                  const float* __restrict__ x) {
    __shared__ __align__(128) uint8_t A_HI[2][128 * 64];
    __shared__ __align__(128) uint8_t A_LO[2][128 * 64];
    __shared__ __align__(128) uint8_t B_HI[2][32 * 64];
    __shared__ __align__(128) uint8_t B_LO[2][32 * 64];

    const int mt   = blockIdx.x;
    const int ks   = blockIdx.y;
    const int tid  = threadIdx.x;
    const int wid  = tid >> 5;
    const int lane = tid & 31;

    const int o = mt * 4 + wid;
    const int u = lane;
    const int m = tid;

    const int xb = tid >> 2, xq = tid & 3;

    const float* const wbase =
        w + (((size_t)(ks * NCH * 2) * OO + o) * CC) * UU + u;
    const float4* const xbase =
        (const float4*)(x + (size_t)xb * KTOT + ks * (NCH * KC)) + xq * 2;

    float  va[32];
    float4 vb[2];

#pragma unroll
    for (int e = 0; e < 32; e++)
        va[e] = wbase[(size_t)(e >> 4) * ISTRIDE + (e & 15) * UU];
    vb[0] = xbase[0];
    vb[1] = xbase[1];

    float acc[2][4][4];
#pragma unroll
    for (int a = 0; a < 2; a++)
#pragma unroll
        for (int b = 0; b < 4; b++)
#pragma unroll
            for (int c = 0; c < 4; c++) acc[a][b][c] = 0.f;

    for (int t = 0; t < NCH; t++) {
        const int p = t & 1;

#pragma unroll
        for (int j = 0; j < 4; j++) {
            uint32_t h[4], l[4];
#pragma unroll
            for (int q = 0; q < 4; q++) {
                float v0 = va[8 * j + 2 * q], v1 = va[8 * j + 2 * q + 1];
                h[q] = pack_bf16(v0, v1);
                float r0 = v0 - __uint_as_float(h[q] << 16);
                float r1 = v1 - __uint_as_float(h[q] & 0xffff0000u);
                l[q] = pack_bf16(r0, r1);
            }
            const uint32_t off = sw64(m, j);
            *(uint4*)(A_HI[p] + off) = make_uint4(h[0], h[1], h[2], h[3]);
            *(uint4*)(A_LO[p] + off) = make_uint4(l[0], l[1], l[2], l[3]);
        }
        {
            float v[8] = {vb[0].x, vb[0].y, vb[0].z, vb[0].w,
                          vb[1].x, vb[1].y, vb[1].z, vb[1].w};
            uint32_t h[4], l[4];
#pragma unroll
            for (int q = 0; q < 4; q++) {
                h[q] = pack_bf16(v[2 * q], v[2 * q + 1]);
                float r0 = v[2 * q]     - __uint_as_float(h[q] << 16);
                float r1 = v[2 * q + 1] - __uint_as_float(h[q] & 0xffff0000u);
                l[q] = pack_bf16(r0, r1);
            }
            const uint32_t off = sw64(xb, xq);
            *(uint4*)(B_HI[p] + off) = make_uint4(h[0], h[1], h[2], h[3]);
            *(uint4*)(B_LO[p] + off) = make_uint4(l[0], l[1], l[2], l[3]);
        }

        if (t + 1 < NCH) {   // prefetch above barrier (round-11 win)
            const float* wp = wbase + (size_t)((t + 1) * 2) * ISTRIDE;
#pragma unroll
            for (int e = 0; e < 32; e++)
                va[e] = wp[(size_t)(e >> 4) * ISTRIDE + (e & 15) * UU];
            const float4* xp = xbase + (t + 1) * (KC / 4);
            vb[0] = xp[0];
            vb[1] = xp[1];
        }

        __syncthreads();

        const uint32_t aHi = smem_u32(A_HI[p]), aLo = smem_u32(A_LO[p]);
        const uint32_t bHi = smem_u32(B_HI[p]), bLo = smem_u32(B_LO[p]);
#pragma unroll
        for (int kt = 0; kt < 2; kt++) {
            uint32_t ahi[2][4], alo[2][4], bhiR[2][4], bloR[2][4];

            const int ar  = (lane & 7) + ((lane >> 3) & 1) * 8;
            const int akg = 2 * kt + (lane >> 4);
#pragma unroll
            for (int m2 = 0; m2 < 2; m2++) {
                const int row = wid * 32 + m2 * 16 + ar;
                const uint32_t off = sw64(row, akg);
                ldsm_x4(ahi[m2], aHi + off);
                ldsm_x4(alo[m2], aLo + off);
            }
            const int bn  = (lane & 7) + ((lane >> 4) & 1) * 8;
            const int bkg = 2 * kt + ((lane >> 3) & 1);
#pragma unroll
            for (int g2 = 0; g2 < 2; g2++) {
                const int n = g2 * 16 + bn;
                const uint32_t off = sw64(n, bkg);
                ldsm_x4(bhiR[g2], bHi + off);
                ldsm_x4(bloR[g2], bLo + off);
            }
#pragma unroll
            for (int m2 = 0; m2 < 2; m2++)
#pragma unroll
                for (int nt = 0; nt < 4; nt++) {
                    const uint32_t bh0 = bhiR[nt >> 1][(nt & 1) * 2];
                    const uint32_t bh1 = bhiR[nt >> 1][(nt & 1) * 2 + 1];
                    const uint32_t bl0 = bloR[nt >> 1][(nt & 1) * 2];
                    const uint32_t bl1 = bloR[nt >> 1][(nt & 1) * 2 + 1];
                    mma_bf16(acc[m2][nt], ahi[m2], bh0, bh1);
                    mma_bf16(acc[m2][nt], alo[m2], bh0, bh1);
                    mma_bf16(acc[m2][nt], ahi[m2], bl0, bl1);
                }
        }
    }

    // ---- epilogue: accumulate D fragments into g_acc[o][u][b] via RED.ADD
    {
        const int gq = lane >> 2, t2 = (lane & 3) * 2;
        float* base = g_acc + (size_t)o * (UU * BB);
#pragma unroll
        for (int m2 = 0; m2 < 2; m2++)
#pragma unroll
            for (int nt = 0; nt < 4; nt++) {
                const int u0 = m2 * 16 + gq;
                const int c  = nt * 8 + t2;
                atomicAdd(base + (size_t)u0 * BB + c,           acc[m2][nt][0]);
                atomicAdd(base + (size_t)u0 * BB + c + 1,       acc[m2][nt][1]);
                atomicAdd(base + (size_t)(u0 + 8) * BB + c,     acc[m2][nt][2]);
                atomicAdd(base + (size_t)(u0 + 8) * BB + c + 1, acc[m2][nt][3]);
            }
    }
}

// ---------------------------------------------------------------------------
// Squash: grid = OO, 1024 threads. Reads the 4KB-per-o accumulator (L2-hot),
// squashes, writes output, then restores zeros to g_acc for the next replay.
// ---------------------------------------------------------------------------
__global__ void __launch_bounds__(1024) reduce_squash(float* __restrict__ out) {
    const int o = blockIdx.x;
    const int t = threadIdx.x;
    const int uu = t >> 5, b = t & 31;

    __shared__ float sblk[UU * 33];    // [u][b] padded
    __shared__ float scale_s[BB];

    float* ap = g_acc + ((size_t)o * UU + uu) * BB + b;
    sblk[uu * 33 + b] = *ap;   // coalesced 128B rows
    *ap = 0.f;                 // restore invariant for next launch/replay
    __syncthreads();

    if (t < BB) {
        float nsq = 0.f;
#pragma unroll
        for (int uv = 0; uv < UU; uv++) {
            float sv = sblk[uv * 33 + t];
            nsq += sv * sv;
        }
        scale_s[t] = sqrtf(nsq) / (1.0f + nsq);
    }
    __syncthreads();

    {   // coalesced output: b2 = t>>5, u2 = t&31
        const int b2 = t >> 5, u2 = t & 31;
        out[(size_t)b2 * (OO * UU) + o * UU + u2] =
            sblk[u2 * 33 + b2] * scale_s[b2];
    }
}

// ---------------------------------------------------------------------------
extern "C" void kernel_launch(void* const* d_in, const int* in_sizes, int n_in,
                              void* d_out, int out_size) {
    const float* x = (const float*)d_in[0];
    const float* w = (const float*)d_in[1];
    if (n_in >= 2 && in_sizes[0] > in_sizes[1]) {   // guard input ordering
        x = (const float*)d_in[1];
        w = (const float*)d_in[0];
    }

    gemm_tc<<<dim3(MT, KS), 128>>>(w, x);
    reduce_squash<<<OO, 1024>>>((float*)d_out);
}